// round 1
// baseline (speedup 1.0000x reference)
#include <cuda_runtime.h>
#include <cuda_bf16.h>
#include <math.h>

// Problem constants
#define B_  2
#define S_  2048
#define H_  2048
#define NH_ 16
#define HD_ 128
#define ROWS_ (B_ * S_)        // 4096
#define QKV_N (3 * H_)         // 6144

// ---------------- scratch (static device globals; no allocation) ----------------
__device__ float g_qkv[(size_t)ROWS_ * QKV_N];            // [4096, 6144]
__device__ float g_q[(size_t)B_ * NH_ * S_ * HD_];        // [b,h,s,d]
__device__ float g_k[(size_t)B_ * NH_ * S_ * HD_];
__device__ float g_v[(size_t)B_ * NH_ * S_ * HD_];
__device__ float g_ctx[(size_t)ROWS_ * H_];               // [b*s, h*d]

// ---------------- SGEMM: C[M,N] = A[M,K] @ B[K,N] + bias[N] ----------------
// 128x128 block tile, BK=8, 256 threads, 8x8 micro-tile (split 4+4 rows/cols)
__global__ __launch_bounds__(256) void sgemm_bias(
    const float* __restrict__ A, const float* __restrict__ Bm,
    const float* __restrict__ bias, float* __restrict__ C,
    int M, int N, int K)
{
    __shared__ float As[8][128];
    __shared__ float Bs[8][128];

    const int tid = threadIdx.x;
    const int bx = blockIdx.x, by = blockIdx.y;
    const int tx = tid & 15, ty = tid >> 4;

    const int a_r = tid >> 1;              // 0..127
    const int a_c = (tid & 1) << 2;        // 0 or 4
    const int b_r = tid >> 5;              // 0..7
    const int b_c = (tid & 31) << 2;       // 0..124

    const float* Ab = A + (size_t)by * 128 * K;
    const float* Bb = Bm + (size_t)bx * 128;

    float acc[8][8];
#pragma unroll
    for (int i = 0; i < 8; i++)
#pragma unroll
        for (int j = 0; j < 8; j++) acc[i][j] = 0.f;

    for (int k0 = 0; k0 < K; k0 += 8) {
        float4 av = *(const float4*)(Ab + (size_t)a_r * K + k0 + a_c);
        As[a_c + 0][a_r] = av.x;
        As[a_c + 1][a_r] = av.y;
        As[a_c + 2][a_r] = av.z;
        As[a_c + 3][a_r] = av.w;
        *(float4*)(&Bs[b_r][b_c]) =
            *(const float4*)(Bb + (size_t)(k0 + b_r) * N + b_c);
        __syncthreads();

#pragma unroll
        for (int k = 0; k < 8; k++) {
            float ra[8], rb[8];
            *(float4*)(ra)     = *(const float4*)(&As[k][ty * 4]);
            *(float4*)(ra + 4) = *(const float4*)(&As[k][64 + ty * 4]);
            *(float4*)(rb)     = *(const float4*)(&Bs[k][tx * 4]);
            *(float4*)(rb + 4) = *(const float4*)(&Bs[k][64 + tx * 4]);
#pragma unroll
            for (int i = 0; i < 8; i++)
#pragma unroll
                for (int j = 0; j < 8; j++)
                    acc[i][j] += ra[i] * rb[j];
        }
        __syncthreads();
    }

#pragma unroll
    for (int i = 0; i < 8; i++) {
        int r = (i < 4) ? (ty * 4 + i) : (64 + ty * 4 + i - 4);
#pragma unroll
        for (int j = 0; j < 8; j++) {
            int c = (j < 4) ? (tx * 4 + j) : (64 + tx * 4 + j - 4);
            C[(size_t)(by * 128 + r) * N + bx * 128 + c] =
                acc[i][j] + bias[bx * 128 + c];
        }
    }
}

// ---------------- RoPE + logn + split/transpose to [b,h,s,d] ----------------
__global__ __launch_bounds__(256) void rope_split(
    const float* __restrict__ qkv,
    const float* __restrict__ cosb, const float* __restrict__ sinb,
    const float* __restrict__ logn,
    float* __restrict__ Q, float* __restrict__ Kt, float* __restrict__ Vt)
{
    int idx = blockIdx.x * blockDim.x + threadIdx.x;   // [b][s][h][d]
    if (idx >= B_ * S_ * NH_ * HD_) return;
    int d = idx & 127;
    int h = (idx >> 7) & 15;
    int s = (idx >> 11) & 2047;
    int b = idx >> 22;

    size_t row = (size_t)(b * S_ + s) * QKV_N;
    int col = h * HD_ + d;

    float cv = cosb[s * HD_ + d];
    float sv = sinb[s * HD_ + d];

    float qv = qkv[row + col];
    float kv = qkv[row + H_ + col];
    float vv = qkv[row + 2 * H_ + col];

    int   dro = (d < 64) ? (d + 64) : (d - 64);
    float sgn = (d < 64) ? -1.f : 1.f;
    float qo = qkv[row + h * HD_ + dro];
    float ko = qkv[row + H_ + h * HD_ + dro];

    float qr = qv * cv + sgn * qo * sv;
    float kr = kv * cv + sgn * ko * sv;

    // fold logn and 1/sqrt(HD) into q
    float ln = logn[s] * 0.08838834764831845f;

    size_t oidx = (((size_t)(b * NH_ + h) * S_ + s) << 7) + d;
    Q[oidx]  = qr * ln;
    Kt[oidx] = kr;
    Vt[oidx] = vv;
}

// ---------------- Flash attention (causal), fp32 ----------------
// grid: (S/64 q-tiles, B*NH), 256 threads
#define BQ 64
#define BKT 64
#define QK_PAD 129
#define V_PAD 132
#define FLASH_SMEM ((2 * BQ * QK_PAD + BKT * V_PAD + BQ * 65 + 3 * BQ) * 4)

__global__ __launch_bounds__(256) void flash_attn(
    const float* __restrict__ Q, const float* __restrict__ K,
    const float* __restrict__ V, float* __restrict__ ctx)
{
    extern __shared__ float sm[];
    float* Qs = sm;                        // [64][129]
    float* Ks = Qs + BQ * QK_PAD;          // [64][129]
    float* Vs = Ks + BKT * QK_PAD;         // [64][132]
    float* Ss = Vs + BKT * V_PAD;          // [64][65]
    float* m_s = Ss + BQ * 65;             // [64]
    float* l_s = m_s + BQ;                 // [64]
    float* al_s = l_s + BQ;                // [64]

    const int qt = blockIdx.x;             // 0..31
    const int bh = blockIdx.y;             // 0..31
    const int tid = threadIdx.x;

    const float* Qb = Q + (size_t)bh * S_ * HD_;
    const float* Kb = K + (size_t)bh * S_ * HD_;
    const float* Vb = V + (size_t)bh * S_ * HD_;

    // load Q tile (float4 global, scalar smem store into padded rows)
    for (int i = tid; i < BQ * (HD_ / 4); i += 256) {
        int r = i >> 5, c4 = (i & 31) << 2;
        float4 v = *(const float4*)(Qb + (size_t)(qt * BQ + r) * HD_ + c4);
        float* p = &Qs[r * QK_PAD + c4];
        p[0] = v.x; p[1] = v.y; p[2] = v.z; p[3] = v.w;
    }
    if (tid < BQ) { m_s[tid] = -INFINITY; l_s[tid] = 0.f; }

    float O[32];
#pragma unroll
    for (int j = 0; j < 32; j++) O[j] = 0.f;
    const int orow = tid >> 2;
    const int oseg = (tid & 3) * 32;

    __syncthreads();

    const int qr0 = (tid >> 4) * 4;
    const int kc0 = (tid & 15) * 4;

    const int nkt = qt + 1;
    for (int kt = 0; kt < nkt; kt++) {
        // load K, V tiles
        for (int i = tid; i < BKT * (HD_ / 4); i += 256) {
            int r = i >> 5, c4 = (i & 31) << 2;
            float4 kvv = *(const float4*)(Kb + (size_t)(kt * BKT + r) * HD_ + c4);
            float* kp = &Ks[r * QK_PAD + c4];
            kp[0] = kvv.x; kp[1] = kvv.y; kp[2] = kvv.z; kp[3] = kvv.w;
            float4 vvv = *(const float4*)(Vb + (size_t)(kt * BKT + r) * HD_ + c4);
            float* vp = &Vs[r * V_PAD + c4];
            vp[0] = vvv.x; vp[1] = vvv.y; vp[2] = vvv.z; vp[3] = vvv.w;
        }
        __syncthreads();

        // scores: 4x4 per thread
        float a[4][4];
#pragma unroll
        for (int i = 0; i < 4; i++)
#pragma unroll
            for (int j = 0; j < 4; j++) a[i][j] = 0.f;

#pragma unroll 4
        for (int d = 0; d < HD_; d++) {
            float qv[4], kv[4];
#pragma unroll
            for (int i = 0; i < 4; i++) qv[i] = Qs[(qr0 + i) * QK_PAD + d];
#pragma unroll
            for (int j = 0; j < 4; j++) kv[j] = Ks[(kc0 + j) * QK_PAD + d];
#pragma unroll
            for (int i = 0; i < 4; i++)
#pragma unroll
                for (int j = 0; j < 4; j++)
                    a[i][j] += qv[i] * kv[j];
        }

        const bool diag = (kt == qt);
#pragma unroll
        for (int i = 0; i < 4; i++) {
            int qg = qt * BQ + qr0 + i;
#pragma unroll
            for (int j = 0; j < 4; j++) {
                int kg = kt * BKT + kc0 + j;
                Ss[(qr0 + i) * 65 + kc0 + j] =
                    (!diag || kg <= qg) ? a[i][j] : -INFINITY;
            }
        }
        __syncthreads();

        // online softmax per row (threads 0..63)
        if (tid < BQ) {
            int r = tid;
            float mold = m_s[r];
            float rowm = -INFINITY;
#pragma unroll 8
            for (int k = 0; k < BKT; k++)
                rowm = fmaxf(rowm, Ss[r * 65 + k]);
            float mnew = fmaxf(mold, rowm);
            float al = __expf(mold - mnew);   // exp(-inf)=0 on first tile
            float sum = 0.f;
#pragma unroll 8
            for (int k = 0; k < BKT; k++) {
                float p = __expf(Ss[r * 65 + k] - mnew);
                Ss[r * 65 + k] = p;
                sum += p;
            }
            l_s[r] = l_s[r] * al + sum;
            m_s[r] = mnew;
            al_s[r] = al;
        }
        __syncthreads();

        // PV accumulation
        float al = al_s[orow];
#pragma unroll
        for (int j = 0; j < 32; j++) O[j] *= al;
        for (int k = 0; k < BKT; k++) {
            float p = Ss[orow * 65 + k];
            const float4* vp = (const float4*)&Vs[k * V_PAD + oseg];
#pragma unroll
            for (int j4 = 0; j4 < 8; j4++) {
                float4 vv = vp[j4];
                O[j4 * 4 + 0] += p * vv.x;
                O[j4 * 4 + 1] += p * vv.y;
                O[j4 * 4 + 2] += p * vv.z;
                O[j4 * 4 + 3] += p * vv.w;
            }
        }
        __syncthreads();
    }

    // write ctx[b, s, h*128 + d]
    float inv_l = 1.f / l_s[orow];
    int b = bh >> 4, h = bh & 15;
    int s = qt * BQ + orow;
    float* outp = g_ctx + (size_t)(b * S_ + s) * H_ + h * HD_ + oseg;
#pragma unroll
    for (int j4 = 0; j4 < 8; j4++) {
        float4 vv;
        vv.x = O[j4 * 4 + 0] * inv_l;
        vv.y = O[j4 * 4 + 1] * inv_l;
        vv.z = O[j4 * 4 + 2] * inv_l;
        vv.w = O[j4 * 4 + 3] * inv_l;
        *(float4*)(outp + j4 * 4) = vv;
    }
    (void)ctx;
}

// ---------------- launch ----------------
extern "C" void kernel_launch(void* const* d_in, const int* in_sizes, int n_in,
                              void* d_out, int out_size)
{
    const float* hidden = (const float*)d_in[0];
    const float* cosb   = (const float*)d_in[1];
    const float* sinb   = (const float*)d_in[2];
    // d_in[3]: attention_mask (pure causal -> implemented directly)
    const float* logn   = (const float*)d_in[4];
    const float* Wc     = (const float*)d_in[5];
    const float* bc     = (const float*)d_in[6];
    const float* Wp     = (const float*)d_in[7];
    const float* bp     = (const float*)d_in[8];
    float* out = (float*)d_out;

    float *qkv, *Q, *Kt, *Vt, *ctx;
    cudaGetSymbolAddress((void**)&qkv, g_qkv);
    cudaGetSymbolAddress((void**)&Q,   g_q);
    cudaGetSymbolAddress((void**)&Kt,  g_k);
    cudaGetSymbolAddress((void**)&Vt,  g_v);
    cudaGetSymbolAddress((void**)&ctx, g_ctx);

    // 1) qkv = hidden @ Wc + bc   [4096,6144]
    sgemm_bias<<<dim3(QKV_N / 128, ROWS_ / 128), 256>>>(
        hidden, Wc, bc, qkv, ROWS_, QKV_N, H_);

    // 2) rope + logn + split to [b,h,s,d]
    {
        int total = B_ * S_ * NH_ * HD_;
        rope_split<<<(total + 255) / 256, 256>>>(qkv, cosb, sinb, logn, Q, Kt, Vt);
    }

    // 3) flash attention -> ctx [4096, 2048]
    cudaFuncSetAttribute(flash_attn,
                         cudaFuncAttributeMaxDynamicSharedMemorySize, FLASH_SMEM);
    flash_attn<<<dim3(S_ / BQ, B_ * NH_), 256, FLASH_SMEM>>>(Q, Kt, Vt, ctx);

    // 4) out = ctx @ Wp + bp      [4096,2048]
    sgemm_bias<<<dim3(H_ / 128, ROWS_ / 128), 256>>>(
        ctx, Wp, bp, out, ROWS_, H_, H_);
}

// round 2
// speedup vs baseline: 4.7744x; 4.7744x over previous
#include <cuda_runtime.h>
#include <cuda_bf16.h>
#include <math.h>
#include <stdint.h>

// Problem constants
#define B_  2
#define S_  2048
#define H_  2048
#define NH_ 16
#define HD_ 128
#define ROWS_ (B_ * S_)        // 4096
#define QKV_N (3 * H_)         // 6144

// ---------------- scratch (static device globals; no allocation) ----------------
__device__ float g_qkv[(size_t)ROWS_ * QKV_N];            // [4096, 6144]
__device__ float g_q[(size_t)B_ * NH_ * S_ * HD_];        // [b,h,s,d]
__device__ float g_k[(size_t)B_ * NH_ * S_ * HD_];
__device__ float g_v[(size_t)B_ * NH_ * S_ * HD_];
__device__ float g_ctx[(size_t)ROWS_ * H_];               // [b*s, h*d]

// ---------------- tf32 helpers ----------------
__device__ __forceinline__ uint32_t f2tf(float x) {
    uint32_t r;
    asm("cvt.rna.tf32.f32 %0, %1;" : "=r"(r) : "f"(x));
    return r;
}

__device__ __forceinline__ void mma_tf32(float* c, const uint32_t* a, const uint32_t* b) {
    asm volatile(
        "mma.sync.aligned.m16n8k8.row.col.f32.tf32.tf32.f32 "
        "{%0,%1,%2,%3}, {%4,%5,%6,%7}, {%8,%9}, {%0,%1,%2,%3};\n"
        : "+f"(c[0]), "+f"(c[1]), "+f"(c[2]), "+f"(c[3])
        : "r"(a[0]), "r"(a[1]), "r"(a[2]), "r"(a[3]),
          "r"(b[0]), "r"(b[1]));
}

// ---------------- TF32 GEMM: C[M,N] = A[M,K] @ B[K,N] + bias ----------------
// 128x128 block tile, BK=16, 256 threads (8 warps), warp tile m64 x n32.
// As: [k][m] (transposed, pad->136), Bs: [k][n] (pad->136) - conflict-free frags.
__global__ __launch_bounds__(256) void gemm_tf32(
    const float* __restrict__ A, const float* __restrict__ Bm,
    const float* __restrict__ bias, float* __restrict__ C,
    int M, int N, int K)
{
    __shared__ uint32_t As[16][136];
    __shared__ uint32_t Bs[16][136];

    const int tid = threadIdx.x;
    const int bx = blockIdx.x, by = blockIdx.y;
    const int warp = tid >> 5, lane = tid & 31;
    const int wm = (warp & 1) * 64;       // warp m offset
    const int wn = (warp >> 1) * 32;      // warp n offset
    const int lr = lane >> 2;             // 0..7
    const int lc = lane & 3;              // 0..3

    const float* Ab = A + (size_t)(by * 128) * K;
    const float* Bb = Bm + (size_t)bx * 128;

    float c[4][4][4];
#pragma unroll
    for (int mt = 0; mt < 4; mt++)
#pragma unroll
        for (int nt = 0; nt < 4; nt++)
#pragma unroll
            for (int j = 0; j < 4; j++) c[mt][nt][j] = 0.f;

    float4 ra[2], rb[2];

    // prologue: load k0=0
#pragma unroll
    for (int i = 0; i < 2; i++) {
        int t = tid + 256 * i;
        int arow = t >> 2, ac = (t & 3) << 2;
        ra[i] = *(const float4*)(Ab + (size_t)arow * K + ac);
        int brow = t >> 5, bc = (t & 31) << 2;
        rb[i] = *(const float4*)(Bb + (size_t)brow * N + bc);
    }
#pragma unroll
    for (int i = 0; i < 2; i++) {
        int t = tid + 256 * i;
        int arow = t >> 2, ac = (t & 3) << 2;
        As[ac + 0][arow] = f2tf(ra[i].x);
        As[ac + 1][arow] = f2tf(ra[i].y);
        As[ac + 2][arow] = f2tf(ra[i].z);
        As[ac + 3][arow] = f2tf(ra[i].w);
        int brow = t >> 5, bc = (t & 31) << 2;
        uint4 bv = { f2tf(rb[i].x), f2tf(rb[i].y), f2tf(rb[i].z), f2tf(rb[i].w) };
        *(uint4*)&Bs[brow][bc] = bv;
    }
    __syncthreads();

    for (int k0 = 0; k0 < K; k0 += 16) {
        bool more = (k0 + 16) < K;
        if (more) {
#pragma unroll
            for (int i = 0; i < 2; i++) {
                int t = tid + 256 * i;
                int arow = t >> 2, ac = (t & 3) << 2;
                ra[i] = *(const float4*)(Ab + (size_t)arow * K + k0 + 16 + ac);
                int brow = t >> 5, bc = (t & 31) << 2;
                rb[i] = *(const float4*)(Bb + (size_t)(k0 + 16 + brow) * N + bc);
            }
        }

#pragma unroll
        for (int ks = 0; ks < 2; ks++) {
            const int kb = ks * 8;
            uint32_t af[4][4], bf[4][2];
#pragma unroll
            for (int mt = 0; mt < 4; mt++) {
                int m0 = wm + mt * 16 + lr;
                af[mt][0] = As[kb + lc][m0];
                af[mt][1] = As[kb + lc][m0 + 8];
                af[mt][2] = As[kb + lc + 4][m0];
                af[mt][3] = As[kb + lc + 4][m0 + 8];
            }
#pragma unroll
            for (int nt = 0; nt < 4; nt++) {
                int n0 = wn + nt * 8 + lr;
                bf[nt][0] = Bs[kb + lc][n0];
                bf[nt][1] = Bs[kb + lc + 4][n0];
            }
#pragma unroll
            for (int mt = 0; mt < 4; mt++)
#pragma unroll
                for (int nt = 0; nt < 4; nt++)
                    mma_tf32(c[mt][nt], af[mt], bf[nt]);
        }
        __syncthreads();
        if (more) {
#pragma unroll
            for (int i = 0; i < 2; i++) {
                int t = tid + 256 * i;
                int arow = t >> 2, ac = (t & 3) << 2;
                As[ac + 0][arow] = f2tf(ra[i].x);
                As[ac + 1][arow] = f2tf(ra[i].y);
                As[ac + 2][arow] = f2tf(ra[i].z);
                As[ac + 3][arow] = f2tf(ra[i].w);
                int brow = t >> 5, bc = (t & 31) << 2;
                uint4 bv = { f2tf(rb[i].x), f2tf(rb[i].y), f2tf(rb[i].z), f2tf(rb[i].w) };
                *(uint4*)&Bs[brow][bc] = bv;
            }
            __syncthreads();
        }
    }

    // epilogue
#pragma unroll
    for (int mt = 0; mt < 4; mt++) {
        int row = by * 128 + wm + mt * 16 + lr;
#pragma unroll
        for (int nt = 0; nt < 4; nt++) {
            int col = bx * 128 + wn + nt * 8 + 2 * lc;
            float b0 = bias[col], b1 = bias[col + 1];
            float2 v0 = { c[mt][nt][0] + b0, c[mt][nt][1] + b1 };
            float2 v1 = { c[mt][nt][2] + b0, c[mt][nt][3] + b1 };
            *(float2*)(C + (size_t)row * N + col) = v0;
            *(float2*)(C + (size_t)(row + 8) * N + col) = v1;
        }
    }
}

// ---------------- RoPE + logn + split/transpose to [b,h,s,d] ----------------
__global__ __launch_bounds__(256) void rope_split(
    const float* __restrict__ qkv,
    const float* __restrict__ cosb, const float* __restrict__ sinb,
    const float* __restrict__ logn,
    float* __restrict__ Q, float* __restrict__ Kt, float* __restrict__ Vt)
{
    int idx = blockIdx.x * blockDim.x + threadIdx.x;   // [b][s][h][d]
    if (idx >= B_ * S_ * NH_ * HD_) return;
    int d = idx & 127;
    int h = (idx >> 7) & 15;
    int s = (idx >> 11) & 2047;
    int b = idx >> 22;

    size_t row = (size_t)(b * S_ + s) * QKV_N;
    int col = h * HD_ + d;

    float cv = cosb[s * HD_ + d];
    float sv = sinb[s * HD_ + d];

    float qv = qkv[row + col];
    float kv = qkv[row + H_ + col];
    float vv = qkv[row + 2 * H_ + col];

    int   dro = (d < 64) ? (d + 64) : (d - 64);
    float sgn = (d < 64) ? -1.f : 1.f;
    float qo = qkv[row + h * HD_ + dro];
    float ko = qkv[row + H_ + h * HD_ + dro];

    float qr = qv * cv + sgn * qo * sv;
    float kr = kv * cv + sgn * ko * sv;

    // fold logn and 1/sqrt(HD) into q
    float ln = logn[s] * 0.08838834764831845f;

    size_t oidx = (((size_t)(b * NH_ + h) * S_ + s) << 7) + d;
    Q[oidx]  = qr * ln;
    Kt[oidx] = kr;
    Vt[oidx] = vv;
}

// ---------------- Flash attention (causal) with tf32 tensor cores ----------------
// BQ=128 q rows per block, BK=64 kv rows per tile, 8 warps, warp owns m16 row slab.
// Qs[128][132], Ks[64][132], Vs[64][136], Ps[128][68] (tf32 bits) = 171008 B smem.
#define FBQ 128
#define FBKT 64
#define QSTR 132
#define VSTR 136
#define PSTR 68
#define FLASH_SMEM ((FBQ*QSTR + FBKT*QSTR + FBKT*VSTR + FBQ*PSTR) * 4)

__global__ __launch_bounds__(256) void flash_tc(
    const float* __restrict__ Q, const float* __restrict__ K,
    const float* __restrict__ V, float* __restrict__ ctx)
{
    extern __shared__ uint32_t fs[];
    uint32_t* Qs = fs;                         // [128][132]
    uint32_t* Ks = Qs + FBQ * QSTR;            // [64][132]
    uint32_t* Vs = Ks + FBKT * QSTR;           // [64][136]
    uint32_t* Ps = Vs + FBKT * VSTR;           // [128][68]

    const int qt = blockIdx.x;                 // 0..15
    const int bh = blockIdx.y;                 // 0..31
    const int tid = threadIdx.x;
    const int warp = tid >> 5, lane = tid & 31;
    const int lr = lane >> 2;                  // 0..7
    const int lc = lane & 3;                   // 0..3

    const float* Qb = Q + ((size_t)bh * S_ + qt * FBQ) * HD_;
    const float* Kb = K + (size_t)bh * S_ * HD_;
    const float* Vb = V + (size_t)bh * S_ * HD_;

    // load Q tile (convert to tf32)
    for (int t = tid; t < FBQ * (HD_ / 4); t += 256) {
        int r = t >> 5, c4 = (t & 31) << 2;
        float4 v = *(const float4*)(Qb + (size_t)r * HD_ + c4);
        uint4 u = { f2tf(v.x), f2tf(v.y), f2tf(v.z), f2tf(v.w) };
        *(uint4*)&Qs[r * QSTR + c4] = u;
    }

    float m0 = -1e30f, m1 = -1e30f;
    float l0 = 0.f, l1 = 0.f;
    float o[16][4];
#pragma unroll
    for (int nt = 0; nt < 16; nt++)
#pragma unroll
        for (int j = 0; j < 4; j++) o[nt][j] = 0.f;

    const int r0 = warp * 16 + lr;             // local q row (0..127)
    const int g0 = qt * FBQ + r0;              // global q row
    const int g1 = g0 + 8;

    const int nkt = 2 * qt + 2;                // kv tiles
    for (int kt = 0; kt < nkt; kt++) {
        // load K,V tile
        for (int t = tid; t < FBKT * (HD_ / 4); t += 256) {
            int r = t >> 5, c4 = (t & 31) << 2;
            float4 kv = *(const float4*)(Kb + (size_t)(kt * FBKT + r) * HD_ + c4);
            uint4 ku = { f2tf(kv.x), f2tf(kv.y), f2tf(kv.z), f2tf(kv.w) };
            *(uint4*)&Ks[r * QSTR + c4] = ku;
            float4 vv = *(const float4*)(Vb + (size_t)(kt * FBKT + r) * HD_ + c4);
            uint4 vu = { f2tf(vv.x), f2tf(vv.y), f2tf(vv.z), f2tf(vv.w) };
            *(uint4*)&Vs[r * VSTR + c4] = vu;
        }
        __syncthreads();

        // ---- S = Q @ K^T  (m16 x n64 per warp) ----
        float s[8][4];
#pragma unroll
        for (int nt = 0; nt < 8; nt++)
#pragma unroll
            for (int j = 0; j < 4; j++) s[nt][j] = 0.f;

#pragma unroll
        for (int ks = 0; ks < 16; ks++) {
            uint32_t a[4];
            const int kb = ks * 8;
            a[0] = Qs[r0 * QSTR + kb + lc];
            a[1] = Qs[(r0 + 8) * QSTR + kb + lc];
            a[2] = Qs[r0 * QSTR + kb + lc + 4];
            a[3] = Qs[(r0 + 8) * QSTR + kb + lc + 4];
#pragma unroll
            for (int nt = 0; nt < 8; nt++) {
                uint32_t b[2];
                int n0 = nt * 8 + lr;
                b[0] = Ks[n0 * QSTR + kb + lc];
                b[1] = Ks[n0 * QSTR + kb + lc + 4];
                mma_tf32(s[nt], a, b);
            }
        }

        // ---- causal mask ----
        if (kt * FBKT + FBKT - 1 > qt * FBQ + warp * 16) {
#pragma unroll
            for (int nt = 0; nt < 8; nt++) {
                int colb = kt * FBKT + nt * 8 + 2 * lc;
                if (colb > g0)     s[nt][0] = -1e30f;
                if (colb + 1 > g0) s[nt][1] = -1e30f;
                if (colb > g1)     s[nt][2] = -1e30f;
                if (colb + 1 > g1) s[nt][3] = -1e30f;
            }
        }

        // ---- online softmax (warp-local, quad reduction) ----
        float mx0 = -1e30f, mx1 = -1e30f;
#pragma unroll
        for (int nt = 0; nt < 8; nt++) {
            mx0 = fmaxf(mx0, fmaxf(s[nt][0], s[nt][1]));
            mx1 = fmaxf(mx1, fmaxf(s[nt][2], s[nt][3]));
        }
        mx0 = fmaxf(mx0, __shfl_xor_sync(0xffffffffu, mx0, 1));
        mx0 = fmaxf(mx0, __shfl_xor_sync(0xffffffffu, mx0, 2));
        mx1 = fmaxf(mx1, __shfl_xor_sync(0xffffffffu, mx1, 1));
        mx1 = fmaxf(mx1, __shfl_xor_sync(0xffffffffu, mx1, 2));

        float nm0 = fmaxf(m0, mx0), nm1 = fmaxf(m1, mx1);
        float al0 = __expf(m0 - nm0), al1 = __expf(m1 - nm1);
        m0 = nm0; m1 = nm1;

        float sum0 = 0.f, sum1 = 0.f;
#pragma unroll
        for (int nt = 0; nt < 8; nt++) {
            s[nt][0] = __expf(s[nt][0] - nm0);
            s[nt][1] = __expf(s[nt][1] - nm0);
            s[nt][2] = __expf(s[nt][2] - nm1);
            s[nt][3] = __expf(s[nt][3] - nm1);
            sum0 += s[nt][0] + s[nt][1];
            sum1 += s[nt][2] + s[nt][3];
        }
        sum0 += __shfl_xor_sync(0xffffffffu, sum0, 1);
        sum0 += __shfl_xor_sync(0xffffffffu, sum0, 2);
        sum1 += __shfl_xor_sync(0xffffffffu, sum1, 1);
        sum1 += __shfl_xor_sync(0xffffffffu, sum1, 2);
        l0 = l0 * al0 + sum0;
        l1 = l1 * al1 + sum1;

#pragma unroll
        for (int nt = 0; nt < 16; nt++) {
            o[nt][0] *= al0; o[nt][1] *= al0;
            o[nt][2] *= al1; o[nt][3] *= al1;
        }

        // ---- store P (tf32) to smem, warp-private rows ----
#pragma unroll
        for (int nt = 0; nt < 8; nt++) {
            int colp = nt * 8 + 2 * lc;
            Ps[r0 * PSTR + colp]           = f2tf(s[nt][0]);
            Ps[r0 * PSTR + colp + 1]       = f2tf(s[nt][1]);
            Ps[(r0 + 8) * PSTR + colp]     = f2tf(s[nt][2]);
            Ps[(r0 + 8) * PSTR + colp + 1] = f2tf(s[nt][3]);
        }
        __syncwarp();

        // ---- O += P @ V  (m16 x n128 per warp) ----
#pragma unroll
        for (int ks = 0; ks < 8; ks++) {
            uint32_t a[4];
            const int kb = ks * 8;
            a[0] = Ps[r0 * PSTR + kb + lc];
            a[1] = Ps[(r0 + 8) * PSTR + kb + lc];
            a[2] = Ps[r0 * PSTR + kb + lc + 4];
            a[3] = Ps[(r0 + 8) * PSTR + kb + lc + 4];
#pragma unroll
            for (int nt = 0; nt < 16; nt++) {
                uint32_t b[2];
                int n0 = nt * 8 + lr;
                b[0] = Vs[(kb + lc) * VSTR + n0];
                b[1] = Vs[(kb + lc + 4) * VSTR + n0];
                mma_tf32(o[nt], a, b);
            }
        }
        __syncthreads();
    }

    // ---- finalize + write ctx [b, s, h*128 + d] ----
    float il0 = 1.f / l0, il1 = 1.f / l1;
    int b = bh >> 4, h = bh & 15;
    float* out0 = ctx + (size_t)(b * S_ + g0) * H_ + h * HD_;
    float* out1 = ctx + (size_t)(b * S_ + g1) * H_ + h * HD_;
#pragma unroll
    for (int nt = 0; nt < 16; nt++) {
        int col = nt * 8 + 2 * lc;
        float2 v0 = { o[nt][0] * il0, o[nt][1] * il0 };
        float2 v1 = { o[nt][2] * il1, o[nt][3] * il1 };
        *(float2*)(out0 + col) = v0;
        *(float2*)(out1 + col) = v1;
    }
}

// ---------------- launch ----------------
extern "C" void kernel_launch(void* const* d_in, const int* in_sizes, int n_in,
                              void* d_out, int out_size)
{
    const float* hidden = (const float*)d_in[0];
    const float* cosb   = (const float*)d_in[1];
    const float* sinb   = (const float*)d_in[2];
    // d_in[3]: attention_mask (pure causal -> implemented directly)
    const float* logn   = (const float*)d_in[4];
    const float* Wc     = (const float*)d_in[5];
    const float* bc     = (const float*)d_in[6];
    const float* Wp     = (const float*)d_in[7];
    const float* bp     = (const float*)d_in[8];
    float* out = (float*)d_out;

    float *qkv, *Q, *Kt, *Vt, *ctx;
    cudaGetSymbolAddress((void**)&qkv, g_qkv);
    cudaGetSymbolAddress((void**)&Q,   g_q);
    cudaGetSymbolAddress((void**)&Kt,  g_k);
    cudaGetSymbolAddress((void**)&Vt,  g_v);
    cudaGetSymbolAddress((void**)&ctx, g_ctx);

    // 1) qkv = hidden @ Wc + bc   [4096,6144]
    gemm_tf32<<<dim3(QKV_N / 128, ROWS_ / 128), 256>>>(
        hidden, Wc, bc, qkv, ROWS_, QKV_N, H_);

    // 2) rope + logn + split to [b,h,s,d]
    {
        int total = B_ * S_ * NH_ * HD_;
        rope_split<<<(total + 255) / 256, 256>>>(qkv, cosb, sinb, logn, Q, Kt, Vt);
    }

    // 3) flash attention (tensor cores) -> ctx [4096, 2048]
    static bool attr_set = false;
    if (!attr_set) {
        cudaFuncSetAttribute(flash_tc,
                             cudaFuncAttributeMaxDynamicSharedMemorySize, FLASH_SMEM);
        attr_set = true;
    }
    flash_tc<<<dim3(S_ / FBQ, B_ * NH_), 256, FLASH_SMEM>>>(Q, Kt, Vt, ctx);

    // 4) out = ctx @ Wp + bp      [4096,2048]
    gemm_tf32<<<dim3(H_ / 128, ROWS_ / 128), 256>>>(
        ctx, Wp, bp, out, ROWS_, H_, H_);
}

// round 3
// speedup vs baseline: 5.7254x; 1.1992x over previous
#include <cuda_runtime.h>
#include <cuda_bf16.h>
#include <math.h>
#include <stdint.h>

// Problem constants
#define B_  2
#define S_  2048
#define H_  2048
#define NH_ 16
#define HD_ 128
#define ROWS_ (B_ * S_)        // 4096
#define QKV_N (3 * H_)         // 6144

// ---------------- scratch (static device globals; no allocation) ----------------
__device__ float g_qkv[(size_t)ROWS_ * QKV_N];            // [4096, 6144]
__device__ float g_q[(size_t)B_ * NH_ * S_ * HD_];        // [b,h,s,d]
__device__ float g_k[(size_t)B_ * NH_ * S_ * HD_];
__device__ float g_v[(size_t)B_ * NH_ * S_ * HD_];
__device__ float g_ctx[(size_t)ROWS_ * H_];               // [b*s, h*d]

// ---------------- helpers ----------------
__device__ __forceinline__ uint32_t f2tf(float x) {
    uint32_t r;
    asm("cvt.rna.tf32.f32 %0, %1;" : "=r"(r) : "f"(x));
    return r;
}

__device__ __forceinline__ void mma_tf32(float* c, const uint32_t* a, const uint32_t* b) {
    asm volatile(
        "mma.sync.aligned.m16n8k8.row.col.f32.tf32.tf32.f32 "
        "{%0,%1,%2,%3}, {%4,%5,%6,%7}, {%8,%9}, {%0,%1,%2,%3};\n"
        : "+f"(c[0]), "+f"(c[1]), "+f"(c[2]), "+f"(c[3])
        : "r"(a[0]), "r"(a[1]), "r"(a[2]), "r"(a[3]),
          "r"(b[0]), "r"(b[1]));
}

__device__ __forceinline__ uint32_t smem_u32(const void* p) {
    return (uint32_t)__cvta_generic_to_shared(p);
}
__device__ __forceinline__ void cp16(uint32_t dst, const void* src) {
    asm volatile("cp.async.cg.shared.global [%0], [%1], 16;" :: "r"(dst), "l"(src));
}
__device__ __forceinline__ void cp_commit() {
    asm volatile("cp.async.commit_group;");
}
template<int N> __device__ __forceinline__ void cp_wait() {
    asm volatile("cp.async.wait_group %0;" :: "n"(N));
}

// ---------------- TF32 GEMM with 4-stage cp.async pipeline ----------------
// 128x128 block tile, BK=16, 256 threads (8 warps), warp tile m64 x n32.
// As: [4][128][20] f32 (m-major, pad 4 -> conflict-free frag loads)
// Bs: [4][16][136] f32 (k-major rows)
#define GA_STG 2560   // 128*20 floats per stage
#define GB_STG 2176   // 16*136 floats per stage
#define GEMM_SMEM ((4 * (GA_STG + GB_STG)) * 4)   // 75776 B

__global__ __launch_bounds__(256) void gemm_tf32(
    const float* __restrict__ A, const float* __restrict__ Bm,
    const float* __restrict__ bias, float* __restrict__ C,
    int M, int N, int K)
{
    extern __shared__ float gsm[];
    float* As = gsm;                    // [4][128][20]
    float* Bs = gsm + 4 * GA_STG;       // [4][16][136]
    const uint32_t as_u = smem_u32(As);
    const uint32_t bs_u = smem_u32(Bs);

    const int tid = threadIdx.x;
    const int bx = blockIdx.x, by = blockIdx.y;
    const int warp = tid >> 5, lane = tid & 31;
    const int wm = (warp & 1) * 64;
    const int wn = (warp >> 1) * 32;
    const int lr = lane >> 2;
    const int lc = lane & 3;

    const float* Ab = A + (size_t)(by * 128) * K;
    const float* Bb = Bm + (size_t)bx * 128;

    // per-thread cp.async coords (2 chunks each for A and B per tile)
    const int am0 = tid >> 1;                 // rows 0..127 (ch=tid -> tid>>2? see below)
    (void)am0;

    const int KT = K >> 4;

    // issue one 16-k tile into stage st
#define ISSUE_TILE(kt, st)                                                        \
    do {                                                                          \
        const float* Asrc = Ab + (kt) * 16;                                       \
        const float* Bsrc = Bb + (size_t)((kt) * 16) * N;                         \
        _Pragma("unroll")                                                         \
        for (int i = 0; i < 2; i++) {                                             \
            int ch = tid + 256 * i;                                               \
            int am = ch >> 2, ac = (ch & 3) << 2;                                 \
            cp16(as_u + (uint32_t)(((st) * GA_STG + am * 20 + ac) * 4),           \
                 Asrc + (size_t)am * K + ac);                                     \
            int bk = ch >> 5, bn = (ch & 31) << 2;                                \
            cp16(bs_u + (uint32_t)(((st) * GB_STG + bk * 136 + bn) * 4),          \
                 Bsrc + (size_t)bk * N + bn);                                     \
        }                                                                         \
    } while (0)

    ISSUE_TILE(0, 0); cp_commit();
    ISSUE_TILE(1, 1); cp_commit();
    ISSUE_TILE(2, 2); cp_commit();

    float c[4][4][4];
#pragma unroll
    for (int mt = 0; mt < 4; mt++)
#pragma unroll
        for (int nt = 0; nt < 4; nt++)
#pragma unroll
            for (int j = 0; j < 4; j++) c[mt][nt][j] = 0.f;

    for (int kt = 0; kt < KT; kt++) {
        cp_wait<2>();
        __syncthreads();
        if (kt + 3 < KT) { ISSUE_TILE(kt + 3, (kt + 3) & 3); }
        cp_commit();

        const int st = kt & 3;
        const float* Ast = As + st * GA_STG;
        const float* Bst = Bs + st * GB_STG;

#pragma unroll
        for (int ks = 0; ks < 2; ks++) {
            const int kb = ks * 8;
            uint32_t af[4][4], bf[4][2];
#pragma unroll
            for (int mt = 0; mt < 4; mt++) {
                const float* ap = Ast + (wm + mt * 16 + lr) * 20 + kb + lc;
                af[mt][0] = f2tf(ap[0]);
                af[mt][1] = f2tf(ap[8 * 20]);
                af[mt][2] = f2tf(ap[4]);
                af[mt][3] = f2tf(ap[8 * 20 + 4]);
            }
#pragma unroll
            for (int nt = 0; nt < 4; nt++) {
                const float* bp = Bst + (kb + lc) * 136 + wn + nt * 8 + lr;
                bf[nt][0] = f2tf(bp[0]);
                bf[nt][1] = f2tf(bp[4 * 136]);
            }
#pragma unroll
            for (int mt = 0; mt < 4; mt++)
#pragma unroll
                for (int nt = 0; nt < 4; nt++)
                    mma_tf32(c[mt][nt], af[mt], bf[nt]);
        }
    }
#undef ISSUE_TILE

    // epilogue
#pragma unroll
    for (int mt = 0; mt < 4; mt++) {
        int row = by * 128 + wm + mt * 16 + lr;
#pragma unroll
        for (int nt = 0; nt < 4; nt++) {
            int col = bx * 128 + wn + nt * 8 + 2 * lc;
            float b0 = bias[col], b1 = bias[col + 1];
            float2 v0 = { c[mt][nt][0] + b0, c[mt][nt][1] + b1 };
            float2 v1 = { c[mt][nt][2] + b0, c[mt][nt][3] + b1 };
            *(float2*)(C + (size_t)row * N + col) = v0;
            *(float2*)(C + (size_t)(row + 8) * N + col) = v1;
        }
    }
}

// ---------------- RoPE + logn + split/transpose to [b,h,s,d] ----------------
__global__ __launch_bounds__(256) void rope_split(
    const float* __restrict__ qkv,
    const float* __restrict__ cosb, const float* __restrict__ sinb,
    const float* __restrict__ logn,
    float* __restrict__ Q, float* __restrict__ Kt, float* __restrict__ Vt)
{
    int idx = blockIdx.x * blockDim.x + threadIdx.x;   // [b][s][h][d]
    if (idx >= B_ * S_ * NH_ * HD_) return;
    int d = idx & 127;
    int h = (idx >> 7) & 15;
    int s = (idx >> 11) & 2047;
    int b = idx >> 22;

    size_t row = (size_t)(b * S_ + s) * QKV_N;
    int col = h * HD_ + d;

    float cv = cosb[s * HD_ + d];
    float sv = sinb[s * HD_ + d];

    float qv = qkv[row + col];
    float kv = qkv[row + H_ + col];
    float vv = qkv[row + 2 * H_ + col];

    int   dro = (d < 64) ? (d + 64) : (d - 64);
    float sgn = (d < 64) ? -1.f : 1.f;
    float qo = qkv[row + h * HD_ + dro];
    float ko = qkv[row + H_ + h * HD_ + dro];

    float qr = qv * cv + sgn * qo * sv;
    float kr = kv * cv + sgn * ko * sv;

    // fold logn and 1/sqrt(HD) into q
    float ln = logn[s] * 0.08838834764831845f;

    size_t oidx = (((size_t)(b * NH_ + h) * S_ + s) << 7) + d;
    Q[oidx]  = qr * ln;
    Kt[oidx] = kr;
    Vt[oidx] = vv;
}

// ---------------- Flash attention (causal), tf32 mma + cp.async KV ----------------
// BQ=128 q rows per block, BK=64 kv rows per tile, 8 warps, warp owns m16 slab.
// Qs[128][132] tf32; Ks[2][64][132] f32; Vs[64][136] f32; Ps[128][68] tf32.
#define FBQ 128
#define FBKT 64
#define QSTR 132
#define KSTR 132
#define VSTR 136
#define PSTR 68
#define FK_STG (FBKT * KSTR)          // 8448 words
#define OFF_K  (FBQ * QSTR)           // 16896
#define OFF_V  (OFF_K + 2 * FK_STG)   // 33792
#define OFF_P  (OFF_V + FBKT * VSTR)  // 42496
#define FLASH_SMEM ((OFF_P + FBQ * PSTR) * 4)   // 204800 B

__global__ __launch_bounds__(256) void flash_tc(
    const float* __restrict__ Q, const float* __restrict__ K,
    const float* __restrict__ V, float* __restrict__ ctx)
{
    extern __shared__ float fsm[];
    uint32_t* Qs = (uint32_t*)fsm;            // tf32
    float*    Ks = fsm + OFF_K;               // raw f32
    float*    Vs = fsm + OFF_V;               // raw f32
    uint32_t* Ps = (uint32_t*)(fsm + OFF_P);  // tf32
    const uint32_t ks_u = smem_u32(Ks);
    const uint32_t vs_u = smem_u32(Vs);

    const int qt = (S_ / FBQ - 1) - blockIdx.x;   // reversed: heavy tiles first
    const int bh = blockIdx.y;
    const int tid = threadIdx.x;
    const int warp = tid >> 5, lane = tid & 31;
    const int lr = lane >> 2;
    const int lc = lane & 3;

    const float* Qb = Q + ((size_t)bh * S_ + qt * FBQ) * HD_;
    const float* Kb = K + (size_t)bh * S_ * HD_;
    const float* Vb = V + (size_t)bh * S_ * HD_;

    // load Q tile (convert to tf32)
    for (int t = tid; t < FBQ * (HD_ / 4); t += 256) {
        int r = t >> 5, c4 = (t & 31) << 2;
        float4 v = *(const float4*)(Qb + (size_t)r * HD_ + c4);
        uint4 u = { f2tf(v.x), f2tf(v.y), f2tf(v.z), f2tf(v.w) };
        *(uint4*)&Qs[r * QSTR + c4] = u;
    }

    const int nkt = 2 * qt + 2;

    // K/V tile cp.async issue: 64 rows x 128 f32 = 2048 float4 chunks, 8/thread
#define ISSUE_KV(base_u, stride, gptr, kt)                                        \
    do {                                                                          \
        const float* src = (gptr) + (size_t)(kt) * FBKT * HD_;                    \
        _Pragma("unroll")                                                         \
        for (int i = 0; i < 8; i++) {                                             \
            int ch = tid + 256 * i;                                               \
            int r = ch >> 5, c4 = (ch & 31) << 2;                                 \
            cp16((base_u) + (uint32_t)((r * (stride) + c4) * 4),                  \
                 src + (size_t)r * HD_ + c4);                                     \
        }                                                                         \
    } while (0)

    // prologue: K(0) -> stage 0
    ISSUE_KV(ks_u, KSTR, Kb, 0);
    cp_commit();

    float m0 = -1e30f, m1 = -1e30f;
    float l0 = 0.f, l1 = 0.f;
    float o[16][4];
#pragma unroll
    for (int nt = 0; nt < 16; nt++)
#pragma unroll
        for (int j = 0; j < 4; j++) o[nt][j] = 0.f;

    const int r0 = warp * 16 + lr;
    const int g0 = qt * FBQ + r0;
    const int g1 = g0 + 8;

    for (int kt = 0; kt < nkt; kt++) {
        // issue V(kt) and prefetch K(kt+1)
        ISSUE_KV(vs_u, VSTR, Vb, kt);
        cp_commit();
        if (kt + 1 < nkt) {
            ISSUE_KV(ks_u + (uint32_t)(((kt + 1) & 1) * FK_STG * 4), KSTR, Kb, kt + 1);
        }
        cp_commit();

        cp_wait<2>();        // K(kt) ready
        __syncthreads();

        const float* Kst = Ks + (kt & 1) * FK_STG;

        // ---- S = Q @ K^T  (m16 x n64 per warp) ----
        float s[8][4];
#pragma unroll
        for (int nt = 0; nt < 8; nt++)
#pragma unroll
            for (int j = 0; j < 4; j++) s[nt][j] = 0.f;

#pragma unroll
        for (int ksx = 0; ksx < 16; ksx++) {
            uint32_t a[4];
            const int kb = ksx * 8;
            a[0] = Qs[r0 * QSTR + kb + lc];
            a[1] = Qs[(r0 + 8) * QSTR + kb + lc];
            a[2] = Qs[r0 * QSTR + kb + lc + 4];
            a[3] = Qs[(r0 + 8) * QSTR + kb + lc + 4];
#pragma unroll
            for (int nt = 0; nt < 8; nt++) {
                uint32_t b[2];
                const float* kp = Kst + (nt * 8 + lr) * KSTR + kb + lc;
                b[0] = f2tf(kp[0]);
                b[1] = f2tf(kp[4]);
                mma_tf32(s[nt], a, b);
            }
        }

        // ---- causal mask ----
        if (kt * FBKT + FBKT - 1 > qt * FBQ + warp * 16) {
#pragma unroll
            for (int nt = 0; nt < 8; nt++) {
                int colb = kt * FBKT + nt * 8 + 2 * lc;
                if (colb > g0)     s[nt][0] = -1e30f;
                if (colb + 1 > g0) s[nt][1] = -1e30f;
                if (colb > g1)     s[nt][2] = -1e30f;
                if (colb + 1 > g1) s[nt][3] = -1e30f;
            }
        }

        // ---- online softmax (warp-local quad reduction) ----
        float mx0 = -1e30f, mx1 = -1e30f;
#pragma unroll
        for (int nt = 0; nt < 8; nt++) {
            mx0 = fmaxf(mx0, fmaxf(s[nt][0], s[nt][1]));
            mx1 = fmaxf(mx1, fmaxf(s[nt][2], s[nt][3]));
        }
        mx0 = fmaxf(mx0, __shfl_xor_sync(0xffffffffu, mx0, 1));
        mx0 = fmaxf(mx0, __shfl_xor_sync(0xffffffffu, mx0, 2));
        mx1 = fmaxf(mx1, __shfl_xor_sync(0xffffffffu, mx1, 1));
        mx1 = fmaxf(mx1, __shfl_xor_sync(0xffffffffu, mx1, 2));

        float nm0 = fmaxf(m0, mx0), nm1 = fmaxf(m1, mx1);
        float al0 = __expf(m0 - nm0), al1 = __expf(m1 - nm1);
        m0 = nm0; m1 = nm1;

        float sum0 = 0.f, sum1 = 0.f;
#pragma unroll
        for (int nt = 0; nt < 8; nt++) {
            s[nt][0] = __expf(s[nt][0] - nm0);
            s[nt][1] = __expf(s[nt][1] - nm0);
            s[nt][2] = __expf(s[nt][2] - nm1);
            s[nt][3] = __expf(s[nt][3] - nm1);
            sum0 += s[nt][0] + s[nt][1];
            sum1 += s[nt][2] + s[nt][3];
        }
        sum0 += __shfl_xor_sync(0xffffffffu, sum0, 1);
        sum0 += __shfl_xor_sync(0xffffffffu, sum0, 2);
        sum1 += __shfl_xor_sync(0xffffffffu, sum1, 1);
        sum1 += __shfl_xor_sync(0xffffffffu, sum1, 2);
        l0 = l0 * al0 + sum0;
        l1 = l1 * al1 + sum1;

#pragma unroll
        for (int nt = 0; nt < 16; nt++) {
            o[nt][0] *= al0; o[nt][1] *= al0;
            o[nt][2] *= al1; o[nt][3] *= al1;
        }

        // ---- store P (tf32), warp-private rows ----
#pragma unroll
        for (int nt = 0; nt < 8; nt++) {
            int colp = nt * 8 + 2 * lc;
            Ps[r0 * PSTR + colp]           = f2tf(s[nt][0]);
            Ps[r0 * PSTR + colp + 1]       = f2tf(s[nt][1]);
            Ps[(r0 + 8) * PSTR + colp]     = f2tf(s[nt][2]);
            Ps[(r0 + 8) * PSTR + colp + 1] = f2tf(s[nt][3]);
        }
        __syncwarp();

        cp_wait<1>();        // V(kt) ready
        __syncthreads();

        // ---- O += P @ V  (m16 x n128 per warp) ----
#pragma unroll
        for (int ksx = 0; ksx < 8; ksx++) {
            uint32_t a[4];
            const int kb = ksx * 8;
            a[0] = Ps[r0 * PSTR + kb + lc];
            a[1] = Ps[(r0 + 8) * PSTR + kb + lc];
            a[2] = Ps[r0 * PSTR + kb + lc + 4];
            a[3] = Ps[(r0 + 8) * PSTR + kb + lc + 4];
#pragma unroll
            for (int nt = 0; nt < 16; nt++) {
                uint32_t b[2];
                const float* vp = Vs + (kb + lc) * VSTR + nt * 8 + lr;
                b[0] = f2tf(vp[0]);
                b[1] = f2tf(vp[4 * VSTR]);
                mma_tf32(o[nt], a, b);
            }
        }
        __syncthreads();     // all PV reads done before next V overwrite
    }
#undef ISSUE_KV

    // ---- finalize + write ctx [b, s, h*128 + d] ----
    float il0 = 1.f / l0, il1 = 1.f / l1;
    int b = bh >> 4, h = bh & 15;
    float* out0 = ctx + (size_t)(b * S_ + g0) * H_ + h * HD_;
    float* out1 = ctx + (size_t)(b * S_ + g1) * H_ + h * HD_;
#pragma unroll
    for (int nt = 0; nt < 16; nt++) {
        int col = nt * 8 + 2 * lc;
        float2 v0 = { o[nt][0] * il0, o[nt][1] * il0 };
        float2 v1 = { o[nt][2] * il1, o[nt][3] * il1 };
        *(float2*)(out0 + col) = v0;
        *(float2*)(out1 + col) = v1;
    }
}

// ---------------- launch ----------------
extern "C" void kernel_launch(void* const* d_in, const int* in_sizes, int n_in,
                              void* d_out, int out_size)
{
    const float* hidden = (const float*)d_in[0];
    const float* cosb   = (const float*)d_in[1];
    const float* sinb   = (const float*)d_in[2];
    // d_in[3]: attention_mask (pure causal -> implemented directly)
    const float* logn   = (const float*)d_in[4];
    const float* Wc     = (const float*)d_in[5];
    const float* bc     = (const float*)d_in[6];
    const float* Wp     = (const float*)d_in[7];
    const float* bp     = (const float*)d_in[8];
    float* out = (float*)d_out;

    float *qkv, *Q, *Kt, *Vt, *ctx;
    cudaGetSymbolAddress((void**)&qkv, g_qkv);
    cudaGetSymbolAddress((void**)&Q,   g_q);
    cudaGetSymbolAddress((void**)&Kt,  g_k);
    cudaGetSymbolAddress((void**)&Vt,  g_v);
    cudaGetSymbolAddress((void**)&ctx, g_ctx);

    cudaFuncSetAttribute(gemm_tf32,
                         cudaFuncAttributeMaxDynamicSharedMemorySize, GEMM_SMEM);
    cudaFuncSetAttribute(flash_tc,
                         cudaFuncAttributeMaxDynamicSharedMemorySize, FLASH_SMEM);

    // 1) qkv = hidden @ Wc + bc   [4096,6144]
    gemm_tf32<<<dim3(QKV_N / 128, ROWS_ / 128), 256, GEMM_SMEM>>>(
        hidden, Wc, bc, qkv, ROWS_, QKV_N, H_);

    // 2) rope + logn + split to [b,h,s,d]
    {
        int total = B_ * S_ * NH_ * HD_;
        rope_split<<<(total + 255) / 256, 256>>>(qkv, cosb, sinb, logn, Q, Kt, Vt);
    }

    // 3) flash attention (tensor cores) -> ctx [4096, 2048]
    flash_tc<<<dim3(S_ / FBQ, B_ * NH_), 256, FLASH_SMEM>>>(Q, Kt, Vt, ctx);

    // 4) out = ctx @ Wp + bp      [4096,2048]
    gemm_tf32<<<dim3(H_ / 128, ROWS_ / 128), 256, GEMM_SMEM>>>(
        ctx, Wp, bp, out, ROWS_, H_, H_);
}

// round 4
// speedup vs baseline: 6.0691x; 1.0600x over previous
#include <cuda_runtime.h>
#include <cuda_bf16.h>
#include <math.h>
#include <stdint.h>

// Problem constants
#define B_  2
#define S_  2048
#define H_  2048
#define NH_ 16
#define HD_ 128
#define ROWS_ (B_ * S_)        // 4096
#define QKV_N (3 * H_)         // 6144

// ---------------- scratch (static device globals; no allocation) ----------------
__device__ float g_qkv[(size_t)ROWS_ * QKV_N];            // [4096, 6144]
__device__ float g_q[(size_t)B_ * NH_ * S_ * HD_];        // [b,h,s,d] tf32-rounded
__device__ float g_k[(size_t)B_ * NH_ * S_ * HD_];        // [b,h,s,d] tf32-rounded
__device__ float g_v[(size_t)B_ * NH_ * S_ * HD_];        // [b,h,d,s] tf32-rounded (transposed!)
__device__ float g_ctx[(size_t)ROWS_ * H_];               // [b*s, h*d] tf32-rounded
__device__ float g_hid_tf[(size_t)ROWS_ * H_];            // tf32-rounded copies
__device__ float g_wc_tf[(size_t)H_ * QKV_N];
__device__ float g_wp_tf[(size_t)H_ * H_];

// ---------------- helpers ----------------
__device__ __forceinline__ uint32_t f2tf(float x) {
    uint32_t r;
    asm("cvt.rna.tf32.f32 %0, %1;" : "=r"(r) : "f"(x));
    return r;
}
__device__ __forceinline__ float f2tff(float x) { return __uint_as_float(f2tf(x)); }

__device__ __forceinline__ void mma_tf32(float* c, const uint32_t* a, const uint32_t* b) {
    asm volatile(
        "mma.sync.aligned.m16n8k8.row.col.f32.tf32.tf32.f32 "
        "{%0,%1,%2,%3}, {%4,%5,%6,%7}, {%8,%9}, {%0,%1,%2,%3};\n"
        : "+f"(c[0]), "+f"(c[1]), "+f"(c[2]), "+f"(c[3])
        : "r"(a[0]), "r"(a[1]), "r"(a[2]), "r"(a[3]),
          "r"(b[0]), "r"(b[1]));
}
__device__ __forceinline__ void ldsm4(uint32_t* r, uint32_t addr) {
    asm volatile("ldmatrix.sync.aligned.m8n8.x4.shared.b16 {%0,%1,%2,%3}, [%4];"
        : "=r"(r[0]), "=r"(r[1]), "=r"(r[2]), "=r"(r[3]) : "r"(addr));
}
__device__ __forceinline__ uint32_t smem_u32(const void* p) {
    return (uint32_t)__cvta_generic_to_shared(p);
}
__device__ __forceinline__ void cp16(uint32_t dst, const void* src) {
    asm volatile("cp.async.cg.shared.global [%0], [%1], 16;" :: "r"(dst), "l"(src));
}
__device__ __forceinline__ void cp_commit() {
    asm volatile("cp.async.commit_group;");
}
template<int N> __device__ __forceinline__ void cp_wait() {
    asm volatile("cp.async.wait_group %0;" :: "n"(N));
}

// ---------------- tf32 pre-round (elementwise) ----------------
__global__ __launch_bounds__(256) void to_tf32k(const float* __restrict__ in,
                                                float* __restrict__ out, int n4)
{
    int i = blockIdx.x * 256 + threadIdx.x;
    if (i < n4) {
        float4 v = ((const float4*)in)[i];
        v.x = f2tff(v.x); v.y = f2tff(v.y); v.z = f2tff(v.z); v.w = f2tff(v.w);
        ((float4*)out)[i] = v;
    }
}

// ---------------- TF32 GEMM, 4-stage cp.async + ldmatrix fragments ----------------
// 128x128 block tile, BK=16, 256 threads (8 warps), warp tile m64 x n32.
// As: [4][128][20] (m-major, pad 4); Bs: [4][16][136] (k-major rows).
#define GA_STG 2560
#define GB_STG 2176
#define GEMM_SMEM ((4 * (GA_STG + GB_STG)) * 4)   // 75776 B

__global__ __launch_bounds__(256) void gemm_tf32(
    const float* __restrict__ A, const float* __restrict__ Bm,
    const float* __restrict__ bias, float* __restrict__ C,
    int M, int N, int K)
{
    extern __shared__ float gsm[];
    float* As = gsm;                    // [4][128][20]
    float* Bs = gsm + 4 * GA_STG;       // [4][16][136]
    const uint32_t as_u = smem_u32(As);

    const int tid = threadIdx.x;
    const int bx = blockIdx.x, by = blockIdx.y;
    const int warp = tid >> 5, lane = tid & 31;
    const int wm = (warp & 1) * 64;
    const int wn = (warp >> 1) * 32;
    const int lr = lane >> 2;
    const int lc = lane & 3;

    // ldmatrix A per-lane offset (bytes): row = wm + (lane&15), kcol = (lane>>4)*4
    const uint32_t a_lane = as_u +
        (uint32_t)(((wm + (lane & 15)) * 20 + ((lane >> 4) << 2)) * 4);

    const float* Ab = A + (size_t)(by * 128) * K;
    const float* Bb = Bm + (size_t)bx * 128;

    const int KT = K >> 4;

#define ISSUE_TILE(kt, st)                                                        \
    do {                                                                          \
        const float* Asrc = Ab + (kt) * 16;                                       \
        const float* Bsrc = Bb + (size_t)((kt) * 16) * N;                         \
        _Pragma("unroll")                                                         \
        for (int i = 0; i < 2; i++) {                                             \
            int ch = tid + 256 * i;                                               \
            int am = ch >> 2, ac = (ch & 3) << 2;                                 \
            cp16(as_u + (uint32_t)(((st) * GA_STG + am * 20 + ac) * 4),           \
                 Asrc + (size_t)am * K + ac);                                     \
            int bk = ch >> 5, bn = (ch & 31) << 2;                                \
            cp16(smem_u32(Bs) + (uint32_t)(((st) * GB_STG + bk * 136 + bn) * 4),  \
                 Bsrc + (size_t)bk * N + bn);                                     \
        }                                                                         \
    } while (0)

    ISSUE_TILE(0, 0); cp_commit();
    ISSUE_TILE(1, 1); cp_commit();
    ISSUE_TILE(2, 2); cp_commit();

    float c[4][4][4];
#pragma unroll
    for (int mt = 0; mt < 4; mt++)
#pragma unroll
        for (int nt = 0; nt < 4; nt++)
#pragma unroll
            for (int j = 0; j < 4; j++) c[mt][nt][j] = 0.f;

    for (int kt = 0; kt < KT; kt++) {
        cp_wait<2>();
        __syncthreads();
        if (kt + 3 < KT) { ISSUE_TILE(kt + 3, (kt + 3) & 3); }
        cp_commit();

        const int st = kt & 3;
        const uint32_t a_st = a_lane + (uint32_t)(st * GA_STG * 4);
        const uint32_t* Bst = (const uint32_t*)(Bs + st * GB_STG) + wn + lr;

#pragma unroll
        for (int ks = 0; ks < 2; ks++) {
            const int kb = ks * 8;
            uint32_t af[4][4], bf[4][2];
#pragma unroll
            for (int mt = 0; mt < 4; mt++)
                ldsm4(af[mt], a_st + (uint32_t)((mt * 16 * 20 + kb) * 4));
#pragma unroll
            for (int nt = 0; nt < 4; nt++) {
                bf[nt][0] = Bst[(kb + lc) * 136 + nt * 8];
                bf[nt][1] = Bst[(kb + lc + 4) * 136 + nt * 8];
            }
#pragma unroll
            for (int mt = 0; mt < 4; mt++)
#pragma unroll
                for (int nt = 0; nt < 4; nt++)
                    mma_tf32(c[mt][nt], af[mt], bf[nt]);
        }
    }
#undef ISSUE_TILE

    // epilogue
#pragma unroll
    for (int mt = 0; mt < 4; mt++) {
        int row = by * 128 + wm + mt * 16 + lr;
#pragma unroll
        for (int nt = 0; nt < 4; nt++) {
            int col = bx * 128 + wn + nt * 8 + 2 * lc;
            float b0 = bias[col], b1 = bias[col + 1];
            float2 v0 = { c[mt][nt][0] + b0, c[mt][nt][1] + b1 };
            float2 v1 = { c[mt][nt][2] + b0, c[mt][nt][3] + b1 };
            *(float2*)(C + (size_t)row * N + col) = v0;
            *(float2*)(C + (size_t)(row + 8) * N + col) = v1;
        }
    }
}

// ---------------- RoPE + logn + split to [b,h,s,d] (Q,K only, tf32-rounded) ----------------
__global__ __launch_bounds__(256) void rope_split(
    const float* __restrict__ qkv,
    const float* __restrict__ cosb, const float* __restrict__ sinb,
    const float* __restrict__ logn,
    float* __restrict__ Q, float* __restrict__ Kt)
{
    int idx = blockIdx.x * blockDim.x + threadIdx.x;   // [b][s][h][d]
    if (idx >= B_ * S_ * NH_ * HD_) return;
    int d = idx & 127;
    int h = (idx >> 7) & 15;
    int s = (idx >> 11) & 2047;
    int b = idx >> 22;

    size_t row = (size_t)(b * S_ + s) * QKV_N;
    int col = h * HD_ + d;

    float cv = cosb[s * HD_ + d];
    float sv = sinb[s * HD_ + d];

    float qv = qkv[row + col];
    float kv = qkv[row + H_ + col];

    int   dro = (d < 64) ? (d + 64) : (d - 64);
    float sgn = (d < 64) ? -1.f : 1.f;
    float qo = qkv[row + h * HD_ + dro];
    float ko = qkv[row + H_ + h * HD_ + dro];

    float qr = qv * cv + sgn * qo * sv;
    float kr = kv * cv + sgn * ko * sv;

    float ln = logn[s] * 0.08838834764831845f;  // fold logn and 1/sqrt(HD) into q

    size_t oidx = (((size_t)(b * NH_ + h) * S_ + s) << 7) + d;
    Q[oidx]  = f2tff(qr * ln);
    Kt[oidx] = f2tff(kr);
}

// ---------------- V transpose: qkv[b,s,h,d] -> Vt[b,h,d,s] (tf32-rounded) ----------------
__global__ __launch_bounds__(256) void vtrans(
    const float* __restrict__ qkv, float* __restrict__ Vt)
{
    __shared__ float t[32][33];
    const int bh = blockIdx.z;
    const int b = bh >> 4, h = bh & 15;
    const int s0 = blockIdx.x * 32, d0 = blockIdx.y * 32;
    const int x = threadIdx.x, y = threadIdx.y;   // 32 x 8

#pragma unroll
    for (int i = 0; i < 32; i += 8)
        t[y + i][x] = qkv[(size_t)(b * S_ + s0 + y + i) * QKV_N + 2 * H_ + h * HD_ + d0 + x];
    __syncthreads();
#pragma unroll
    for (int i = 0; i < 32; i += 8)
        Vt[((size_t)bh * HD_ + d0 + y + i) * S_ + s0 + x] = f2tff(t[x][y + i]);
}

// ---------------- Flash attention: tf32 mma + cp.async + ldmatrix everywhere ----------------
// BQ=128 q rows, BK=64 kv per tile, 8 warps (m16 slab each).
// Qs[128][132]; Ks[2][64][132]; Vs[128][68] (d-major!); Ps[128][68].
#define FBQ 128
#define FBKT 64
#define QSTR 132
#define KSTR 132
#define VSTR 68
#define PSTR 68
#define FK_STG (FBKT * KSTR)          // 8448 words
#define OFF_K  (FBQ * QSTR)           // 16896
#define OFF_V  (OFF_K + 2 * FK_STG)   // 33792
#define OFF_P  (OFF_V + HD_ * VSTR)   // 42496
#define FLASH_SMEM ((OFF_P + FBQ * PSTR) * 4)   // 204800 B

__global__ __launch_bounds__(256) void flash_tc(
    const float* __restrict__ Q, const float* __restrict__ K,
    const float* __restrict__ V, float* __restrict__ ctx)
{
    extern __shared__ float fsm[];
    uint32_t* Qs = (uint32_t*)fsm;
    float*    Ks = fsm + OFF_K;
    float*    Vs = fsm + OFF_V;               // [d=128][kv=64] pad->68
    uint32_t* Ps = (uint32_t*)(fsm + OFF_P);
    const uint32_t qs_u = smem_u32(Qs);
    const uint32_t ks_u = smem_u32(Ks);
    const uint32_t vs_u = smem_u32(Vs);
    const uint32_t ps_u = smem_u32(Ps);

    const int qt = (S_ / FBQ - 1) - blockIdx.x;   // heavy tiles first
    const int bh = blockIdx.y;
    const int tid = threadIdx.x;
    const int warp = tid >> 5, lane = tid & 31;
    const int lr = lane >> 2;
    const int lc = lane & 3;

    // ldmatrix lane geometry
    const int la_m = lane & 15;                // A-frag row within m16
    const int la_k = (lane >> 4) << 2;         // A-frag k subcol (0/4)
    const int lb_r = (lane & 7) + ((lane >> 4) << 3);   // B-frag row within n16
    const int lb_c = ((lane >> 3) & 1) << 2;            // B-frag k subcol (0/4)

    const uint32_t q_lane = qs_u + (uint32_t)(((warp * 16 + la_m) * QSTR + la_k) * 4);
    const uint32_t p_lane = ps_u + (uint32_t)(((warp * 16 + la_m) * PSTR + la_k) * 4);

    const float* Qb = Q + ((size_t)bh * S_ + qt * FBQ) * HD_;
    const float* Kb = K + (size_t)bh * S_ * HD_;
    const float* Vb = V + (size_t)bh * HD_ * S_;   // [d][s]

    // load Q tile (already tf32-rounded)
    for (int t = tid; t < FBQ * (HD_ / 4); t += 256) {
        int r = t >> 5, c4 = (t & 31) << 2;
        *(uint4*)&Qs[r * QSTR + c4] = *(const uint4*)(Qb + (size_t)r * HD_ + c4);
    }

    const int nkt = 2 * qt + 2;

#define ISSUE_K(kt)                                                               \
    do {                                                                          \
        const float* src = Kb + (size_t)(kt) * FBKT * HD_;                        \
        uint32_t dst = ks_u + (uint32_t)(((kt) & 1) * FK_STG * 4);                \
        _Pragma("unroll")                                                         \
        for (int i = 0; i < 8; i++) {                                             \
            int ch = tid + 256 * i;                                               \
            int r = ch >> 5, c4 = (ch & 31) << 2;                                 \
            cp16(dst + (uint32_t)((r * KSTR + c4) * 4), src + (size_t)r * HD_ + c4); \
        }                                                                         \
    } while (0)
#define ISSUE_V(kt)                                                               \
    do {                                                                          \
        const float* src = Vb + (size_t)(kt) * FBKT;                              \
        _Pragma("unroll")                                                         \
        for (int i = 0; i < 8; i++) {                                             \
            int ch = tid + 256 * i;                                               \
            int r = ch >> 4, c4 = (ch & 15) << 2;                                 \
            cp16(vs_u + (uint32_t)((r * VSTR + c4) * 4), src + (size_t)r * S_ + c4); \
        }                                                                         \
    } while (0)

    ISSUE_K(0);
    cp_commit();

    float m0 = -1e30f, m1 = -1e30f;
    float l0 = 0.f, l1 = 0.f;
    float o[16][4];
#pragma unroll
    for (int nt = 0; nt < 16; nt++)
#pragma unroll
        for (int j = 0; j < 4; j++) o[nt][j] = 0.f;

    const int r0 = warp * 16 + lr;
    const int g0 = qt * FBQ + r0;
    const int g1 = g0 + 8;

    for (int kt = 0; kt < nkt; kt++) {
        ISSUE_V(kt);
        cp_commit();
        if (kt + 1 < nkt) { ISSUE_K(kt + 1); }
        cp_commit();

        cp_wait<2>();        // K(kt) ready
        __syncthreads();

        const uint32_t kst_u = ks_u + (uint32_t)((kt & 1) * FK_STG * 4);

        // ---- S = Q @ K^T (m16 x n64 per warp) ----
        float s[8][4];
#pragma unroll
        for (int nt = 0; nt < 8; nt++)
#pragma unroll
            for (int j = 0; j < 4; j++) s[nt][j] = 0.f;

#pragma unroll
        for (int ksx = 0; ksx < 16; ksx++) {
            const int kb = ksx * 8;
            uint32_t a[4];
            ldsm4(a, q_lane + (uint32_t)(kb * 4));
#pragma unroll
            for (int p = 0; p < 4; p++) {
                uint32_t r[4];
                ldsm4(r, kst_u + (uint32_t)(((p * 16 + lb_r) * KSTR + kb + lb_c) * 4));
                mma_tf32(s[2 * p], a, r);
                mma_tf32(s[2 * p + 1], a, r + 2);
            }
        }

        // ---- causal mask ----
        if (kt * FBKT + FBKT - 1 > qt * FBQ + warp * 16) {
#pragma unroll
            for (int nt = 0; nt < 8; nt++) {
                int colb = kt * FBKT + nt * 8 + 2 * lc;
                if (colb > g0)     s[nt][0] = -1e30f;
                if (colb + 1 > g0) s[nt][1] = -1e30f;
                if (colb > g1)     s[nt][2] = -1e30f;
                if (colb + 1 > g1) s[nt][3] = -1e30f;
            }
        }

        // ---- online softmax (warp-local quad reduction) ----
        float mx0 = -1e30f, mx1 = -1e30f;
#pragma unroll
        for (int nt = 0; nt < 8; nt++) {
            mx0 = fmaxf(mx0, fmaxf(s[nt][0], s[nt][1]));
            mx1 = fmaxf(mx1, fmaxf(s[nt][2], s[nt][3]));
        }
        mx0 = fmaxf(mx0, __shfl_xor_sync(0xffffffffu, mx0, 1));
        mx0 = fmaxf(mx0, __shfl_xor_sync(0xffffffffu, mx0, 2));
        mx1 = fmaxf(mx1, __shfl_xor_sync(0xffffffffu, mx1, 1));
        mx1 = fmaxf(mx1, __shfl_xor_sync(0xffffffffu, mx1, 2));

        float nm0 = fmaxf(m0, mx0), nm1 = fmaxf(m1, mx1);
        float al0 = __expf(m0 - nm0), al1 = __expf(m1 - nm1);
        m0 = nm0; m1 = nm1;

        float sum0 = 0.f, sum1 = 0.f;
#pragma unroll
        for (int nt = 0; nt < 8; nt++) {
            s[nt][0] = __expf(s[nt][0] - nm0);
            s[nt][1] = __expf(s[nt][1] - nm0);
            s[nt][2] = __expf(s[nt][2] - nm1);
            s[nt][3] = __expf(s[nt][3] - nm1);
            sum0 += s[nt][0] + s[nt][1];
            sum1 += s[nt][2] + s[nt][3];
        }
        sum0 += __shfl_xor_sync(0xffffffffu, sum0, 1);
        sum0 += __shfl_xor_sync(0xffffffffu, sum0, 2);
        sum1 += __shfl_xor_sync(0xffffffffu, sum1, 1);
        sum1 += __shfl_xor_sync(0xffffffffu, sum1, 2);
        l0 = l0 * al0 + sum0;
        l1 = l1 * al1 + sum1;

#pragma unroll
        for (int nt = 0; nt < 16; nt++) {
            o[nt][0] *= al0; o[nt][1] *= al0;
            o[nt][2] *= al1; o[nt][3] *= al1;
        }

        // ---- store P (tf32), warp-private rows ----
#pragma unroll
        for (int nt = 0; nt < 8; nt++) {
            int colp = nt * 8 + 2 * lc;
            Ps[r0 * PSTR + colp]           = f2tf(s[nt][0]);
            Ps[r0 * PSTR + colp + 1]       = f2tf(s[nt][1]);
            Ps[(r0 + 8) * PSTR + colp]     = f2tf(s[nt][2]);
            Ps[(r0 + 8) * PSTR + colp + 1] = f2tf(s[nt][3]);
        }
        __syncwarp();

        cp_wait<1>();        // V(kt) ready
        __syncthreads();

        // ---- O += P @ V (m16 x n128 per warp); V is d-major -> ldmatrix ----
#pragma unroll
        for (int ksx = 0; ksx < 8; ksx++) {
            const int kb = ksx * 8;
            uint32_t a[4];
            ldsm4(a, p_lane + (uint32_t)(kb * 4));
#pragma unroll
            for (int p = 0; p < 8; p++) {
                uint32_t r[4];
                ldsm4(r, vs_u + (uint32_t)(((p * 16 + lb_r) * VSTR + kb + lb_c) * 4));
                mma_tf32(o[2 * p], a, r);
                mma_tf32(o[2 * p + 1], a, r + 2);
            }
        }
        __syncthreads();     // all PV reads done before next V overwrite
    }
#undef ISSUE_K
#undef ISSUE_V

    // ---- finalize + write ctx (tf32-rounded for proj GEMM) ----
    float il0 = 1.f / l0, il1 = 1.f / l1;
    int b = bh >> 4, h = bh & 15;
    float* out0 = ctx + (size_t)(b * S_ + g0) * H_ + h * HD_;
    float* out1 = ctx + (size_t)(b * S_ + g1) * H_ + h * HD_;
#pragma unroll
    for (int nt = 0; nt < 16; nt++) {
        int col = nt * 8 + 2 * lc;
        float2 v0 = { f2tff(o[nt][0] * il0), f2tff(o[nt][1] * il0) };
        float2 v1 = { f2tff(o[nt][2] * il1), f2tff(o[nt][3] * il1) };
        *(float2*)(out0 + col) = v0;
        *(float2*)(out1 + col) = v1;
    }
}

// ---------------- launch ----------------
extern "C" void kernel_launch(void* const* d_in, const int* in_sizes, int n_in,
                              void* d_out, int out_size)
{
    const float* hidden = (const float*)d_in[0];
    const float* cosb   = (const float*)d_in[1];
    const float* sinb   = (const float*)d_in[2];
    // d_in[3]: attention_mask (pure causal -> implemented directly)
    const float* logn   = (const float*)d_in[4];
    const float* Wc     = (const float*)d_in[5];
    const float* bc     = (const float*)d_in[6];
    const float* Wp     = (const float*)d_in[7];
    const float* bp     = (const float*)d_in[8];
    float* out = (float*)d_out;

    float *qkv, *Q, *Kt, *Vt, *ctx, *hid_tf, *wc_tf, *wp_tf;
    cudaGetSymbolAddress((void**)&qkv,    g_qkv);
    cudaGetSymbolAddress((void**)&Q,      g_q);
    cudaGetSymbolAddress((void**)&Kt,     g_k);
    cudaGetSymbolAddress((void**)&Vt,     g_v);
    cudaGetSymbolAddress((void**)&ctx,    g_ctx);
    cudaGetSymbolAddress((void**)&hid_tf, g_hid_tf);
    cudaGetSymbolAddress((void**)&wc_tf,  g_wc_tf);
    cudaGetSymbolAddress((void**)&wp_tf,  g_wp_tf);

    cudaFuncSetAttribute(gemm_tf32,
                         cudaFuncAttributeMaxDynamicSharedMemorySize, GEMM_SMEM);
    cudaFuncSetAttribute(flash_tc,
                         cudaFuncAttributeMaxDynamicSharedMemorySize, FLASH_SMEM);

    // 0) pre-round GEMM operands to tf32
    {
        int n4h = (ROWS_ * H_) / 4;
        to_tf32k<<<(n4h + 255) / 256, 256>>>(hidden, hid_tf, n4h);
        int n4c = (H_ * QKV_N) / 4;
        to_tf32k<<<(n4c + 255) / 256, 256>>>(Wc, wc_tf, n4c);
        int n4p = (H_ * H_) / 4;
        to_tf32k<<<(n4p + 255) / 256, 256>>>(Wp, wp_tf, n4p);
    }

    // 1) qkv = hidden @ Wc + bc   [4096,6144]
    gemm_tf32<<<dim3(QKV_N / 128, ROWS_ / 128), 256, GEMM_SMEM>>>(
        hid_tf, wc_tf, bc, qkv, ROWS_, QKV_N, H_);

    // 2) rope + logn -> Q,K [b,h,s,d];  V transpose -> [b,h,d,s]
    {
        int total = B_ * S_ * NH_ * HD_;
        rope_split<<<(total + 255) / 256, 256>>>(qkv, cosb, sinb, logn, Q, Kt);
        vtrans<<<dim3(S_ / 32, HD_ / 32, B_ * NH_), dim3(32, 8)>>>(qkv, Vt);
    }

    // 3) flash attention -> ctx [4096, 2048]
    flash_tc<<<dim3(S_ / FBQ, B_ * NH_), 256, FLASH_SMEM>>>(Q, Kt, Vt, ctx);

    // 4) out = ctx @ Wp + bp      [4096,2048]
    gemm_tf32<<<dim3(H_ / 128, ROWS_ / 128), 256, GEMM_SMEM>>>(
        ctx, wp_tf, bp, out, ROWS_, H_, H_);
}